// round 13
// baseline (speedup 1.0000x reference)
#include <cuda_runtime.h>
#include <cuda_bf16.h>
#include <math.h>
#include <stdint.h>

// Problem dims (fixed by the dataset)
#define NX   4096
#define NY   4096
#define DIN  1024
#define HID  1024
#define DOUT 1024

typedef __nv_bfloat16 bf16;

// ---------------------------------------------------------------------------
// Scratch: __device__ globals (allocation-free)
// ---------------------------------------------------------------------------
__device__ bf16 g_xh[(size_t)NX * DIN],  g_xl[(size_t)NX * DIN];
__device__ bf16 g_yh[(size_t)NY * DIN],  g_yl[(size_t)NY * DIN];
__device__ bf16 g_Wqh[(size_t)HID * DIN], g_Wql[(size_t)HID * DIN];
__device__ bf16 g_Wkh[(size_t)HID * DIN], g_Wkl[(size_t)HID * DIN];
__device__ bf16 g_Wvh[(size_t)DOUT * DIN], g_Wvl[(size_t)DOUT * DIN];
__device__ bf16 g_Qh[(size_t)NX * HID],  g_Ql[(size_t)NX * HID];
__device__ bf16 g_Kh[(size_t)NY * HID],  g_Kl[(size_t)NY * HID];
__device__ bf16 g_VTh[(size_t)DOUT * NY], g_VTl[(size_t)DOUT * NY];
__device__ bf16 g_Ph[(size_t)NX * NY],   g_Pl[(size_t)NX * NY];
__device__ float g_S[(size_t)NX * NY];

// ---------------------------------------------------------------------------
// Helpers
// ---------------------------------------------------------------------------
__device__ __forceinline__ uint32_t smem_u32(const void* p) {
    uint32_t a;
    asm("{ .reg .u64 t; cvta.to.shared.u64 t, %1; cvt.u32.u64 %0, t; }" : "=r"(a) : "l"(p));
    return a;
}
__device__ __forceinline__ void ldm_x4(uint32_t* r, uint32_t addr) {
    asm volatile("ldmatrix.sync.aligned.m8n8.x4.shared.b16 {%0,%1,%2,%3}, [%4];"
                 : "=r"(r[0]), "=r"(r[1]), "=r"(r[2]), "=r"(r[3]) : "r"(addr));
}
__device__ __forceinline__ void mma_bf16(float* c, const uint32_t* a,
                                         uint32_t b0, uint32_t b1) {
    asm volatile(
        "mma.sync.aligned.m16n8k16.row.col.f32.bf16.bf16.f32 "
        "{%0,%1,%2,%3}, {%4,%5,%6,%7}, {%8,%9}, {%0,%1,%2,%3};"
        : "+f"(c[0]), "+f"(c[1]), "+f"(c[2]), "+f"(c[3])
        : "r"(a[0]), "r"(a[1]), "r"(a[2]), "r"(a[3]), "r"(b0), "r"(b1));
}
// fp32 pair -> (hi bf16x2, lo bf16x2); x lands in the low 16 bits
__device__ __forceinline__ void cvt_split(float x, float y, uint32_t& h, uint32_t& l) {
    asm("cvt.rn.bf16x2.f32 %0, %1, %2;" : "=r"(h) : "f"(y), "f"(x));
    float hx = __uint_as_float(h << 16);
    float hy = __uint_as_float(h & 0xffff0000u);
    asm("cvt.rn.bf16x2.f32 %0, %1, %2;" : "=r"(l) : "f"(y - hy), "f"(x - hx));
}
__device__ __forceinline__ void cpa16(uint32_t d, const void* s) {
    asm volatile("cp.async.cg.shared.global [%0], [%1], 16;" :: "r"(d), "l"(s) : "memory");
}
#define CP_COMMIT() asm volatile("cp.async.commit_group;" ::: "memory")
#define CP_WAIT0()  asm volatile("cp.async.wait_group 0;" ::: "memory")

// ---------------------------------------------------------------------------
// Fused elementwise fp32 -> (hi, lo) bf16 split, up to 3 tensors per launch
// (keeps launch count at 2 so the ncu capture lands on the scores GEMM)
// ---------------------------------------------------------------------------
__global__ __launch_bounds__(256)
void split3_kernel(const float* __restrict__ p0, bf16* __restrict__ h0, bf16* __restrict__ l0, int n0,
                   const float* __restrict__ p1, bf16* __restrict__ h1, bf16* __restrict__ l1, int n1,
                   const float* __restrict__ p2, bf16* __restrict__ h2, bf16* __restrict__ l2, int n2)
{
    int i = blockIdx.x * 256 + threadIdx.x;
    const float* in; bf16 *hi, *lo;
    if (i < n0)                { in = p0; hi = h0; lo = l0; }
    else if (i < n0 + n1)      { i -= n0; in = p1; hi = h1; lo = l1; }
    else if (i < n0 + n1 + n2) { i -= n0 + n1; in = p2; hi = h2; lo = l2; }
    else return;
    float4 v = reinterpret_cast<const float4*>(in)[i];
    uint32_t a0, b0, a1, b1;
    cvt_split(v.x, v.y, a0, b0);
    cvt_split(v.z, v.w, a1, b1);
    reinterpret_cast<uint2*>(hi)[i] = make_uint2(a0, a1);
    reinterpret_cast<uint2*>(lo)[i] = make_uint2(b0, b1);
}

// ---------------------------------------------------------------------------
// bf16-split tensor-core GEMM (pre-split operands, cp.async 2-stage pipeline)
//   acc = A @ B^T ; v = scale*acc + bias_col[N] + bias_row[M]
//   Cf (fp32) and/or (Chi, Clo) bf16-split outputs.
// CTA tile 128x128, BK=32, 256 threads (8 warps, 4x2), warp tile 32x64.
// 2 CTAs/SM -> 16 warps/SM = 4/SMSP to cover HMMA dependency gaps.
// Live regs ~115 < 128 cap from launch_bounds(256,2): no spills.
// ONE __syncthreads per chunk; lookahead strictly 1 (2 stages, no aliasing).
// ---------------------------------------------------------------------------
#define PITCH 40                        // bf16 elems per smem row (80 B)
#define T_AHI 0
#define T_ALO (128 * PITCH * 2)         // 10240
#define T_BHI (2 * 128 * PITCH * 2)     // 20480
#define T_BLO (3 * 128 * PITCH * 2)     // 30720
#define STAGE_BYTES (4 * 128 * PITCH * 2)   // 40960
#define SM_TOTAL (2 * STAGE_BYTES)          // 81920

__global__ __launch_bounds__(256, 2)
void gemm_bf16(const bf16* __restrict__ Ahi, const bf16* __restrict__ Alo,
               const bf16* __restrict__ Bhi, const bf16* __restrict__ Blo,
               const float* __restrict__ bias_col, const float* __restrict__ bias_row,
               float* __restrict__ Cf, bf16* __restrict__ Chi, bf16* __restrict__ Clo,
               int M, int N, int K, float scale)
{
    extern __shared__ __align__(128) char smem[];
    const uint32_t sbase = smem_u32(smem);

    const int tid    = threadIdx.x;
    const int lane   = tid & 31;
    const int wid    = tid >> 5;        // 0..7
    const int warp_m = wid & 3;         // 4 slabs of 32 rows
    const int warp_n = wid >> 2;        // 2 slabs of 64 cols
    const int row0   = blockIdx.y * 128;
    const int col0   = blockIdx.x * 128;

    const bf16* pAh = Ahi + (size_t)row0 * K;
    const bf16* pAl = Alo + (size_t)row0 * K;
    const bf16* pBh = Bhi + (size_t)col0 * K;
    const bf16* pBl = Blo + (size_t)col0 * K;

    // loader geometry: 256 threads, base row = tid>>2 (0..63), 2 row-steps of 64;
    // seg = (tid&3)*8 bf16 (16B)
    const int l_r  = tid >> 2;
    const int l_sg = (tid & 3) * 8;

    float acc[2][8][4];
#pragma unroll
    for (int mf = 0; mf < 2; mf++)
#pragma unroll
        for (int nf = 0; nf < 8; nf++)
#pragma unroll
            for (int e = 0; e < 4; e++) acc[mf][nf][e] = 0.0f;

    // ldmatrix addressing (validated geometry)
    const int a_row  = lane & 15;
    const int a_kh   = (lane >> 4) << 3;
    const int bg     = lane >> 3;
    const int b_nrow = ((bg >> 1) << 3) + (lane & 7);
    const int b_kh   = (bg & 1) << 3;

    const int nch = K >> 5;

    auto issue = [&](int c) {
        const uint32_t st = sbase + (c & 1) * STAGE_BYTES;
        const int kofs = c * 32;
#pragma unroll
        for (int rt = 0; rt < 2; rt++) {
            const int r = l_r + rt * 64;
            const size_t go = (size_t)r * K + kofs + l_sg;
            const uint32_t so = (uint32_t)(r * PITCH + l_sg) * 2;
            cpa16(st + T_AHI + so, pAh + go);
            cpa16(st + T_ALO + so, pAl + go);
            cpa16(st + T_BHI + so, pBh + go);
            cpa16(st + T_BLO + so, pBl + go);
        }
    };

    issue(0); CP_COMMIT();

    for (int c = 0; c < nch; c++) {
        CP_WAIT0();                 // chunk c (sole pending group) has landed
        __syncthreads();            // (a) chunk c visible to all warps
                                    // (b) all warps finished computing c-1, so
                                    //     the other stage is reusable
        if (c + 1 < nch) { issue(c + 1); CP_COMMIT(); }   // other stage — safe

        const uint32_t st = sbase + (c & 1) * STAGE_BYTES;
#pragma unroll
        for (int kk = 0; kk < 32; kk += 16) {
            uint32_t ah[2][4], al[2][4];
#pragma unroll
            for (int mf = 0; mf < 2; mf++) {
                uint32_t ra = st + ((warp_m * 32 + mf * 16 + a_row) * PITCH + kk + a_kh) * 2;
                ldm_x4(ah[mf], ra + T_AHI);
                ldm_x4(al[mf], ra + T_ALO);
            }
#pragma unroll
            for (int ng = 0; ng < 4; ng++) {
                uint32_t bh[4], bl[4];
                uint32_t rb = st + ((warp_n * 64 + ng * 16 + b_nrow) * PITCH + kk + b_kh) * 2;
                ldm_x4(bh, rb + T_BHI);
                ldm_x4(bl, rb + T_BLO);
                // split-term-major order: same-accumulator reuse distance = 4
#pragma unroll
                for (int s = 0; s < 2; s++)
#pragma unroll
                    for (int mf = 0; mf < 2; mf++)
                        mma_bf16(acc[mf][2 * ng + s], ah[mf], bh[2 * s], bh[2 * s + 1]);
#pragma unroll
                for (int s = 0; s < 2; s++)
#pragma unroll
                    for (int mf = 0; mf < 2; mf++)
                        mma_bf16(acc[mf][2 * ng + s], ah[mf], bl[2 * s], bl[2 * s + 1]);
#pragma unroll
                for (int s = 0; s < 2; s++)
#pragma unroll
                    for (int mf = 0; mf < 2; mf++)
                        mma_bf16(acc[mf][2 * ng + s], al[mf], bh[2 * s], bh[2 * s + 1]);
            }
        }
    }

    // ---- epilogue ----
    const int mrow = lane >> 2;
    const int ncol = (lane & 3) * 2;
#pragma unroll
    for (int mf = 0; mf < 2; mf++) {
        const int m0 = row0 + warp_m * 32 + mf * 16 + mrow;
        const float br0 = bias_row ? bias_row[m0]     : 0.0f;
        const float br8 = bias_row ? bias_row[m0 + 8] : 0.0f;
#pragma unroll
        for (int nf = 0; nf < 8; nf++) {
            const int n = col0 + warp_n * 64 + nf * 8 + ncol;
            float bc0 = 0.0f, bc1 = 0.0f;
            if (bias_col) { bc0 = bias_col[n]; bc1 = bias_col[n + 1]; }
            float* cc = acc[mf][nf];
            float v00 = cc[0] * scale + bc0 + br0;
            float v01 = cc[1] * scale + bc1 + br0;
            float v10 = cc[2] * scale + bc0 + br8;
            float v11 = cc[3] * scale + bc1 + br8;
            if (Cf) {
                *reinterpret_cast<float2*>(Cf + (size_t)m0 * N + n)       = make_float2(v00, v01);
                *reinterpret_cast<float2*>(Cf + (size_t)(m0 + 8) * N + n) = make_float2(v10, v11);
            }
            if (Chi) {
                uint32_t h, l;
                cvt_split(v00, v01, h, l);
                *reinterpret_cast<uint32_t*>(Chi + (size_t)m0 * N + n) = h;
                *reinterpret_cast<uint32_t*>(Clo + (size_t)m0 * N + n) = l;
                cvt_split(v10, v11, h, l);
                *reinterpret_cast<uint32_t*>(Chi + (size_t)(m0 + 8) * N + n) = h;
                *reinterpret_cast<uint32_t*>(Clo + (size_t)(m0 + 8) * N + n) = l;
            }
        }
    }
}

// ---------------------------------------------------------------------------
// Row softmax over N=4096 fp32 scores -> hi/lo bf16 probabilities
// ---------------------------------------------------------------------------
__device__ __forceinline__ float warp_max(float v) {
#pragma unroll
    for (int o = 16; o > 0; o >>= 1) v = fmaxf(v, __shfl_xor_sync(0xffffffffu, v, o));
    return v;
}
__device__ __forceinline__ float warp_sum(float v) {
#pragma unroll
    for (int o = 16; o > 0; o >>= 1) v += __shfl_xor_sync(0xffffffffu, v, o);
    return v;
}

__global__ __launch_bounds__(256)
void softmax_rows_kernel(const float* __restrict__ S, bf16* __restrict__ Ph,
                         bf16* __restrict__ Pl, int N)
{
    constexpr int T = 256;
    constexpr int PER = 4096 / T;
    const int row = blockIdx.x;
    const float* p = S + (size_t)row * N;
    bf16* ph = Ph + (size_t)row * N;
    bf16* pl = Pl + (size_t)row * N;
    const int tid = threadIdx.x;
    const int wid = tid >> 5, lid = tid & 31;
    __shared__ float red[8];

    float v[PER];
    float mx = -INFINITY;
#pragma unroll
    for (int i = 0; i < PER; i++) { v[i] = p[tid + i * T]; mx = fmaxf(mx, v[i]); }
    mx = warp_max(mx);
    if (lid == 0) red[wid] = mx;
    __syncthreads();
    { float m = (lid < 8) ? red[lid] : -INFINITY; m = warp_max(m); mx = __shfl_sync(0xffffffffu, m, 0); }

    float sum = 0.0f;
#pragma unroll
    for (int i = 0; i < PER; i++) { v[i] = __expf(v[i] - mx); sum += v[i]; }
    sum = warp_sum(sum);
    __syncthreads();
    if (lid == 0) red[wid] = sum;
    __syncthreads();
    { float s = (lid < 8) ? red[lid] : 0.0f; s = warp_sum(s); sum = __shfl_sync(0xffffffffu, s, 0); }

    const float inv = 1.0f / sum;
#pragma unroll
    for (int i = 0; i < PER; i++) {
        float pv = v[i] * inv;
        bf16 h = __float2bfloat16_rn(pv);
        bf16 l = __float2bfloat16_rn(pv - __bfloat162float(h));
        ph[tid + i * T] = h;
        pl[tid + i * T] = l;
    }
}

// ---------------------------------------------------------------------------
// kernel_launch
// ---------------------------------------------------------------------------
extern "C" void kernel_launch(void* const* d_in, const int* in_sizes, int n_in,
                              void* d_out, int out_size)
{
    (void)in_sizes; (void)n_in; (void)out_size;
    const float* x  = (const float*)d_in[0];
    const float* y  = (const float*)d_in[1];
    const float* Wq = (const float*)d_in[2];
    const float* bq = (const float*)d_in[3];
    const float* Wk = (const float*)d_in[4];
    const float* bk = (const float*)d_in[5];
    const float* Wv = (const float*)d_in[6];
    const float* bv = (const float*)d_in[7];
    float* out = (float*)d_out;

    bf16 *xh, *xl, *yh, *yl, *Wqh, *Wql, *Wkh, *Wkl, *Wvh, *Wvl;
    bf16 *Qh, *Ql, *Kh, *Kl, *VTh, *VTl, *Ph, *Pl;
    float* S;
    cudaGetSymbolAddress((void**)&xh,  g_xh);  cudaGetSymbolAddress((void**)&xl,  g_xl);
    cudaGetSymbolAddress((void**)&yh,  g_yh);  cudaGetSymbolAddress((void**)&yl,  g_yl);
    cudaGetSymbolAddress((void**)&Wqh, g_Wqh); cudaGetSymbolAddress((void**)&Wql, g_Wql);
    cudaGetSymbolAddress((void**)&Wkh, g_Wkh); cudaGetSymbolAddress((void**)&Wkl, g_Wkl);
    cudaGetSymbolAddress((void**)&Wvh, g_Wvh); cudaGetSymbolAddress((void**)&Wvl, g_Wvl);
    cudaGetSymbolAddress((void**)&Qh,  g_Qh);  cudaGetSymbolAddress((void**)&Ql,  g_Ql);
    cudaGetSymbolAddress((void**)&Kh,  g_Kh);  cudaGetSymbolAddress((void**)&Kl,  g_Kl);
    cudaGetSymbolAddress((void**)&VTh, g_VTh); cudaGetSymbolAddress((void**)&VTl, g_VTl);
    cudaGetSymbolAddress((void**)&Ph,  g_Ph);  cudaGetSymbolAddress((void**)&Pl,  g_Pl);
    cudaGetSymbolAddress((void**)&S,   g_S);

    cudaFuncSetAttribute(gemm_bf16, cudaFuncAttributeMaxDynamicSharedMemorySize, SM_TOTAL);

    const float inv_sqrt_h = 1.0f / 32.0f;

    // Pre-split inputs — exactly TWO launches
    {
        const int nx4 = NX * DIN / 4, ny4 = NY * DIN / 4, nw4 = HID * DIN / 4;
        int totA = nx4 + nw4 + nw4;
        split3_kernel<<<(totA + 255) / 256, 256>>>(
            x, xh, xl, nx4, Wq, Wqh, Wql, nw4, Wk, Wkh, Wkl, nw4);
        int totB = ny4 + nw4;
        split3_kernel<<<(totB + 255) / 256, 256>>>(
            y, yh, yl, ny4, Wv, Wvh, Wvl, nw4, nullptr, nullptr, nullptr, 0);
    }

    // Q = x @ Wq^T + bq     -> bf16 hi/lo   [4096,1024]
    gemm_bf16<<<dim3(HID/128, NX/128), 256, SM_TOTAL>>>(
        xh, xl, Wqh, Wql, bq, nullptr, nullptr, Qh, Ql, NX, HID, DIN, 1.0f);
    // K = y @ Wk^T + bk     -> bf16 hi/lo   [4096,1024]
    gemm_bf16<<<dim3(HID/128, NY/128), 256, SM_TOTAL>>>(
        yh, yl, Wkh, Wkl, bk, nullptr, nullptr, Kh, Kl, NY, HID, DIN, 1.0f);
    // V^T = Wv @ y^T + bv(row) -> bf16 hi/lo [1024,4096]
    gemm_bf16<<<dim3(NY/128, DOUT/128), 256, SM_TOTAL>>>(
        Wvh, Wvl, yh, yl, nullptr, bv, nullptr, VTh, VTl, DOUT, NY, DIN, 1.0f);
    // S = (Q @ K^T)/32      -> fp32         [4096,4096]   <- profiled launch
    gemm_bf16<<<dim3(NY/128, NX/128), 256, SM_TOTAL>>>(
        Qh, Ql, Kh, Kl, nullptr, nullptr, S, nullptr, nullptr, NX, NY, HID, inv_sqrt_h);
    // softmax rows -> attn hi/lo bf16
    softmax_rows_kernel<<<NX, 256>>>(S, Ph, Pl, NY);
    // out = attn @ V = P @ VT^T -> fp32     [4096,1024]
    gemm_bf16<<<dim3(DOUT/128, NX/128), 256, SM_TOTAL>>>(
        Ph, Pl, VTh, VTl, nullptr, nullptr, out, nullptr, nullptr, NX, DOUT, NY, 1.0f);
}

// round 15
// speedup vs baseline: 1.0604x; 1.0604x over previous
#include <cuda_runtime.h>
#include <cuda_bf16.h>
#include <math.h>
#include <stdint.h>

// Problem dims (fixed by the dataset)
#define NX   4096
#define NY   4096
#define DIN  1024
#define HID  1024
#define DOUT 1024

typedef __nv_bfloat16 bf16;

// ---------------------------------------------------------------------------
// Scratch: __device__ globals (allocation-free)
// ---------------------------------------------------------------------------
__device__ bf16 g_xh[(size_t)NX * DIN],  g_xl[(size_t)NX * DIN];
__device__ bf16 g_yh[(size_t)NY * DIN],  g_yl[(size_t)NY * DIN];
__device__ bf16 g_Wqh[(size_t)HID * DIN], g_Wql[(size_t)HID * DIN];
__device__ bf16 g_Wkh[(size_t)HID * DIN], g_Wkl[(size_t)HID * DIN];
__device__ bf16 g_Wvh[(size_t)DOUT * DIN], g_Wvl[(size_t)DOUT * DIN];
__device__ bf16 g_Qh[(size_t)NX * HID],  g_Ql[(size_t)NX * HID];
__device__ bf16 g_Kh[(size_t)NY * HID],  g_Kl[(size_t)NY * HID];
__device__ bf16 g_VTh[(size_t)DOUT * NY], g_VTl[(size_t)DOUT * NY];
__device__ bf16 g_Ph[(size_t)NX * NY],   g_Pl[(size_t)NX * NY];
__device__ float g_S[(size_t)NX * NY];

// ---------------------------------------------------------------------------
// Helpers
// ---------------------------------------------------------------------------
__device__ __forceinline__ uint32_t smem_u32(const void* p) {
    uint32_t a;
    asm("{ .reg .u64 t; cvta.to.shared.u64 t, %1; cvt.u32.u64 %0, t; }" : "=r"(a) : "l"(p));
    return a;
}
__device__ __forceinline__ void ldm_x4(uint32_t* r, uint32_t addr) {
    asm volatile("ldmatrix.sync.aligned.m8n8.x4.shared.b16 {%0,%1,%2,%3}, [%4];"
                 : "=r"(r[0]), "=r"(r[1]), "=r"(r[2]), "=r"(r[3]) : "r"(addr));
}
__device__ __forceinline__ void mma_bf16(float* c, const uint32_t* a,
                                         uint32_t b0, uint32_t b1) {
    asm volatile(
        "mma.sync.aligned.m16n8k16.row.col.f32.bf16.bf16.f32 "
        "{%0,%1,%2,%3}, {%4,%5,%6,%7}, {%8,%9}, {%0,%1,%2,%3};"
        : "+f"(c[0]), "+f"(c[1]), "+f"(c[2]), "+f"(c[3])
        : "r"(a[0]), "r"(a[1]), "r"(a[2]), "r"(a[3]), "r"(b0), "r"(b1));
}
// fp32 pair -> (hi bf16x2, lo bf16x2); x lands in the low 16 bits
__device__ __forceinline__ void cvt_split(float x, float y, uint32_t& h, uint32_t& l) {
    asm("cvt.rn.bf16x2.f32 %0, %1, %2;" : "=r"(h) : "f"(y), "f"(x));
    float hx = __uint_as_float(h << 16);
    float hy = __uint_as_float(h & 0xffff0000u);
    asm("cvt.rn.bf16x2.f32 %0, %1, %2;" : "=r"(l) : "f"(y - hy), "f"(x - hx));
}
__device__ __forceinline__ void cpa16(uint32_t d, const void* s) {
    asm volatile("cp.async.cg.shared.global [%0], [%1], 16;" :: "r"(d), "l"(s) : "memory");
}
#define CP_COMMIT() asm volatile("cp.async.commit_group;" ::: "memory")
#define CP_WAIT0()  asm volatile("cp.async.wait_group 0;" ::: "memory")

// ---------------------------------------------------------------------------
// Fused elementwise fp32 -> (hi, lo) bf16 split, up to 3 tensors per launch
// (keeps launch count at 2 so the ncu capture lands on a GEMM)
// ---------------------------------------------------------------------------
__global__ __launch_bounds__(256)
void split3_kernel(const float* __restrict__ p0, bf16* __restrict__ h0, bf16* __restrict__ l0, int n0,
                   const float* __restrict__ p1, bf16* __restrict__ h1, bf16* __restrict__ l1, int n1,
                   const float* __restrict__ p2, bf16* __restrict__ h2, bf16* __restrict__ l2, int n2)
{
    int i = blockIdx.x * 256 + threadIdx.x;
    const float* in; bf16 *hi, *lo;
    if (i < n0)                { in = p0; hi = h0; lo = l0; }
    else if (i < n0 + n1)      { i -= n0; in = p1; hi = h1; lo = l1; }
    else if (i < n0 + n1 + n2) { i -= n0 + n1; in = p2; hi = h2; lo = l2; }
    else return;
    float4 v = reinterpret_cast<const float4*>(in)[i];
    uint32_t a0, b0, a1, b1;
    cvt_split(v.x, v.y, a0, b0);
    cvt_split(v.z, v.w, a1, b1);
    reinterpret_cast<uint2*>(hi)[i] = make_uint2(a0, a1);
    reinterpret_cast<uint2*>(lo)[i] = make_uint2(b0, b1);
}

// ---------------------------------------------------------------------------
// bf16-split tensor-core GEMM (pre-split operands, cp.async 2-stage pipeline)
//   acc = A @ B^T ; v = scale*acc + bias_col[N] + bias_row[M]
//   Cf (fp32) and/or (Chi, Clo) bf16-split outputs.
// CTA tile 128x128, BK=32, 128 threads (4 warps, 2x2), warp tile 64x64,
// 2 CTAs/SM (R12 champion config). NEW: flattened (kk,ng) steps with
// double-buffered B-fragment prefetch one step ahead, hiding ldmatrix
// latency under the MMA stream.
// ---------------------------------------------------------------------------
#define PITCH 40                        // bf16 elems per smem row (80 B)
#define T_AHI 0
#define T_ALO (128 * PITCH * 2)         // 10240
#define T_BHI (2 * 128 * PITCH * 2)     // 20480
#define T_BLO (3 * 128 * PITCH * 2)     // 30720
#define STAGE_BYTES (4 * 128 * PITCH * 2)   // 40960
#define SM_TOTAL (2 * STAGE_BYTES)          // 81920

__global__ __launch_bounds__(128, 2)
void gemm_bf16(const bf16* __restrict__ Ahi, const bf16* __restrict__ Alo,
               const bf16* __restrict__ Bhi, const bf16* __restrict__ Blo,
               const float* __restrict__ bias_col, const float* __restrict__ bias_row,
               float* __restrict__ Cf, bf16* __restrict__ Chi, bf16* __restrict__ Clo,
               int M, int N, int K, float scale)
{
    extern __shared__ __align__(128) char smem[];
    const uint32_t sbase = smem_u32(smem);

    const int tid    = threadIdx.x;
    const int lane   = tid & 31;
    const int wid    = tid >> 5;        // 0..3
    const int warp_m = wid & 1;         // 2 slabs of 64 rows
    const int warp_n = wid >> 1;        // 2 slabs of 64 cols
    const int row0   = blockIdx.y * 128;
    const int col0   = blockIdx.x * 128;

    const bf16* pAh = Ahi + (size_t)row0 * K;
    const bf16* pAl = Alo + (size_t)row0 * K;
    const bf16* pBh = Bhi + (size_t)col0 * K;
    const bf16* pBl = Blo + (size_t)col0 * K;

    // loader geometry: base row = tid>>2 (0..31), 4 row-steps of 32; seg 16B
    const int l_r  = tid >> 2;
    const int l_sg = (tid & 3) * 8;

    float acc[4][8][4];
#pragma unroll
    for (int mf = 0; mf < 4; mf++)
#pragma unroll
        for (int nf = 0; nf < 8; nf++)
#pragma unroll
            for (int e = 0; e < 4; e++) acc[mf][nf][e] = 0.0f;

    // ldmatrix addressing (validated geometry)
    const int a_row  = lane & 15;
    const int a_kh   = (lane >> 4) << 3;
    const int bg     = lane >> 3;
    const int b_nrow = ((bg >> 1) << 3) + (lane & 7);
    const int b_kh   = (bg & 1) << 3;

    const int nch = K >> 5;

    auto issue = [&](int c) {
        const uint32_t st = sbase + (c & 1) * STAGE_BYTES;
        const int kofs = c * 32;
#pragma unroll
        for (int rt = 0; rt < 4; rt++) {
            const int r = l_r + rt * 32;
            const size_t go = (size_t)r * K + kofs + l_sg;
            const uint32_t so = (uint32_t)(r * PITCH + l_sg) * 2;
            cpa16(st + T_AHI + so, pAh + go);
            cpa16(st + T_ALO + so, pAl + go);
            cpa16(st + T_BHI + so, pBh + go);
            cpa16(st + T_BLO + so, pBl + go);
        }
    };

    issue(0); CP_COMMIT();

    uint32_t ah[4][4], al[4][4];
    uint32_t bh[2][4], bl[2][4];

    for (int c = 0; c < nch; c++) {
        CP_WAIT0();                 // chunk c (sole pending group) has landed
        __syncthreads();            // chunk c visible; other stage reusable
        if (c + 1 < nch) { issue(c + 1); CP_COMMIT(); }   // other stage — safe

        const uint32_t st = sbase + (c & 1) * STAGE_BYTES;

        // head loads: A frags for kk=0, B frags for step 0
#pragma unroll
        for (int mf = 0; mf < 4; mf++) {
            uint32_t ra = st + ((warp_m * 64 + mf * 16 + a_row) * PITCH + a_kh) * 2;
            ldm_x4(ah[mf], ra + T_AHI);
            ldm_x4(al[mf], ra + T_ALO);
        }
        {
            uint32_t rb = st + ((warp_n * 64 + b_nrow) * PITCH + b_kh) * 2;
            ldm_x4(bh[0], rb + T_BHI);
            ldm_x4(bl[0], rb + T_BLO);
        }

        // 8 flattened steps: t -> (kk = (t>>2)*16, ng = t&3)
#pragma unroll
        for (int t = 0; t < 8; t++) {
            const int cur = t & 1, nxt = cur ^ 1;
            const int ng  = t & 3;

            // prefetch B frags for step t+1 (lands under this step's MMAs)
            if (t < 7) {
                const int kkn = ((t + 1) >> 2) * 16;
                const int ngn = (t + 1) & 3;
                uint32_t rb = st + ((warp_n * 64 + ngn * 16 + b_nrow) * PITCH + kkn + b_kh) * 2;
                ldm_x4(bh[nxt], rb + T_BHI);
                ldm_x4(bl[nxt], rb + T_BLO);
            }
            // A frags for kk=16 at the kk boundary
            if (t == 4) {
#pragma unroll
                for (int mf = 0; mf < 4; mf++) {
                    uint32_t ra = st + ((warp_m * 64 + mf * 16 + a_row) * PITCH + 16 + a_kh) * 2;
                    ldm_x4(ah[mf], ra + T_AHI);
                    ldm_x4(al[mf], ra + T_ALO);
                }
            }

            // 24 MMAs, split-term-major (same-acc reuse distance 8)
#pragma unroll
            for (int s = 0; s < 2; s++)
#pragma unroll
                for (int mf = 0; mf < 4; mf++)
                    mma_bf16(acc[mf][2 * ng + s], ah[mf], bh[cur][2 * s], bh[cur][2 * s + 1]);
#pragma unroll
            for (int s = 0; s < 2; s++)
#pragma unroll
                for (int mf = 0; mf < 4; mf++)
                    mma_bf16(acc[mf][2 * ng + s], ah[mf], bl[cur][2 * s], bl[cur][2 * s + 1]);
#pragma unroll
            for (int s = 0; s < 2; s++)
#pragma unroll
                for (int mf = 0; mf < 4; mf++)
                    mma_bf16(acc[mf][2 * ng + s], al[mf], bh[cur][2 * s], bh[cur][2 * s + 1]);
        }
    }

    // ---- epilogue ----
    const int mrow = lane >> 2;
    const int ncol = (lane & 3) * 2;
#pragma unroll
    for (int mf = 0; mf < 4; mf++) {
        const int m0 = row0 + warp_m * 64 + mf * 16 + mrow;
        const float br0 = bias_row ? bias_row[m0]     : 0.0f;
        const float br8 = bias_row ? bias_row[m0 + 8] : 0.0f;
#pragma unroll
        for (int nf = 0; nf < 8; nf++) {
            const int n = col0 + warp_n * 64 + nf * 8 + ncol;
            float bc0 = 0.0f, bc1 = 0.0f;
            if (bias_col) { bc0 = bias_col[n]; bc1 = bias_col[n + 1]; }
            float* cc = acc[mf][nf];
            float v00 = cc[0] * scale + bc0 + br0;
            float v01 = cc[1] * scale + bc1 + br0;
            float v10 = cc[2] * scale + bc0 + br8;
            float v11 = cc[3] * scale + bc1 + br8;
            if (Cf) {
                *reinterpret_cast<float2*>(Cf + (size_t)m0 * N + n)       = make_float2(v00, v01);
                *reinterpret_cast<float2*>(Cf + (size_t)(m0 + 8) * N + n) = make_float2(v10, v11);
            }
            if (Chi) {
                uint32_t h, l;
                cvt_split(v00, v01, h, l);
                *reinterpret_cast<uint32_t*>(Chi + (size_t)m0 * N + n) = h;
                *reinterpret_cast<uint32_t*>(Clo + (size_t)m0 * N + n) = l;
                cvt_split(v10, v11, h, l);
                *reinterpret_cast<uint32_t*>(Chi + (size_t)(m0 + 8) * N + n) = h;
                *reinterpret_cast<uint32_t*>(Clo + (size_t)(m0 + 8) * N + n) = l;
            }
        }
    }
}

// ---------------------------------------------------------------------------
// Row softmax over N=4096 fp32 scores -> hi/lo bf16 probabilities
// ---------------------------------------------------------------------------
__device__ __forceinline__ float warp_max(float v) {
#pragma unroll
    for (int o = 16; o > 0; o >>= 1) v = fmaxf(v, __shfl_xor_sync(0xffffffffu, v, o));
    return v;
}
__device__ __forceinline__ float warp_sum(float v) {
#pragma unroll
    for (int o = 16; o > 0; o >>= 1) v += __shfl_xor_sync(0xffffffffu, v, o);
    return v;
}

__global__ __launch_bounds__(256)
void softmax_rows_kernel(const float* __restrict__ S, bf16* __restrict__ Ph,
                         bf16* __restrict__ Pl, int N)
{
    constexpr int T = 256;
    constexpr int PER = 4096 / T;
    const int row = blockIdx.x;
    const float* p = S + (size_t)row * N;
    bf16* ph = Ph + (size_t)row * N;
    bf16* pl = Pl + (size_t)row * N;
    const int tid = threadIdx.x;
    const int wid = tid >> 5, lid = tid & 31;
    __shared__ float red[8];

    float v[PER];
    float mx = -INFINITY;
#pragma unroll
    for (int i = 0; i < PER; i++) { v[i] = p[tid + i * T]; mx = fmaxf(mx, v[i]); }
    mx = warp_max(mx);
    if (lid == 0) red[wid] = mx;
    __syncthreads();
    { float m = (lid < 8) ? red[lid] : -INFINITY; m = warp_max(m); mx = __shfl_sync(0xffffffffu, m, 0); }

    float sum = 0.0f;
#pragma unroll
    for (int i = 0; i < PER; i++) { v[i] = __expf(v[i] - mx); sum += v[i]; }
    sum = warp_sum(sum);
    __syncthreads();
    if (lid == 0) red[wid] = sum;
    __syncthreads();
    { float s = (lid < 8) ? red[lid] : 0.0f; s = warp_sum(s); sum = __shfl_sync(0xffffffffu, s, 0); }

    const float inv = 1.0f / sum;
#pragma unroll
    for (int i = 0; i < PER; i++) {
        float pv = v[i] * inv;
        bf16 h = __float2bfloat16_rn(pv);
        bf16 l = __float2bfloat16_rn(pv - __bfloat162float(h));
        ph[tid + i * T] = h;
        pl[tid + i * T] = l;
    }
}

// ---------------------------------------------------------------------------
// kernel_launch
// ---------------------------------------------------------------------------
extern "C" void kernel_launch(void* const* d_in, const int* in_sizes, int n_in,
                              void* d_out, int out_size)
{
    (void)in_sizes; (void)n_in; (void)out_size;
    const float* x  = (const float*)d_in[0];
    const float* y  = (const float*)d_in[1];
    const float* Wq = (const float*)d_in[2];
    const float* bq = (const float*)d_in[3];
    const float* Wk = (const float*)d_in[4];
    const float* bk = (const float*)d_in[5];
    const float* Wv = (const float*)d_in[6];
    const float* bv = (const float*)d_in[7];
    float* out = (float*)d_out;

    bf16 *xh, *xl, *yh, *yl, *Wqh, *Wql, *Wkh, *Wkl, *Wvh, *Wvl;
    bf16 *Qh, *Ql, *Kh, *Kl, *VTh, *VTl, *Ph, *Pl;
    float* S;
    cudaGetSymbolAddress((void**)&xh,  g_xh);  cudaGetSymbolAddress((void**)&xl,  g_xl);
    cudaGetSymbolAddress((void**)&yh,  g_yh);  cudaGetSymbolAddress((void**)&yl,  g_yl);
    cudaGetSymbolAddress((void**)&Wqh, g_Wqh); cudaGetSymbolAddress((void**)&Wql, g_Wql);
    cudaGetSymbolAddress((void**)&Wkh, g_Wkh); cudaGetSymbolAddress((void**)&Wkl, g_Wkl);
    cudaGetSymbolAddress((void**)&Wvh, g_Wvh); cudaGetSymbolAddress((void**)&Wvl, g_Wvl);
    cudaGetSymbolAddress((void**)&Qh,  g_Qh);  cudaGetSymbolAddress((void**)&Ql,  g_Ql);
    cudaGetSymbolAddress((void**)&Kh,  g_Kh);  cudaGetSymbolAddress((void**)&Kl,  g_Kl);
    cudaGetSymbolAddress((void**)&VTh, g_VTh); cudaGetSymbolAddress((void**)&VTl, g_VTl);
    cudaGetSymbolAddress((void**)&Ph,  g_Ph);  cudaGetSymbolAddress((void**)&Pl,  g_Pl);
    cudaGetSymbolAddress((void**)&S,   g_S);

    cudaFuncSetAttribute(gemm_bf16, cudaFuncAttributeMaxDynamicSharedMemorySize, SM_TOTAL);

    const float inv_sqrt_h = 1.0f / 32.0f;

    // Pre-split inputs — exactly TWO launches
    {
        const int nx4 = NX * DIN / 4, ny4 = NY * DIN / 4, nw4 = HID * DIN / 4;
        int totA = nx4 + nw4 + nw4;
        split3_kernel<<<(totA + 255) / 256, 256>>>(
            x, xh, xl, nx4, Wq, Wqh, Wql, nw4, Wk, Wkh, Wkl, nw4);
        int totB = ny4 + nw4;
        split3_kernel<<<(totB + 255) / 256, 256>>>(
            y, yh, yl, ny4, Wv, Wvh, Wvl, nw4, nullptr, nullptr, nullptr, 0);
    }

    // Q = x @ Wq^T + bq     -> bf16 hi/lo   [4096,1024]
    gemm_bf16<<<dim3(HID/128, NX/128), 128, SM_TOTAL>>>(
        xh, xl, Wqh, Wql, bq, nullptr, nullptr, Qh, Ql, NX, HID, DIN, 1.0f);
    // K = y @ Wk^T + bk     -> bf16 hi/lo   [4096,1024]
    gemm_bf16<<<dim3(HID/128, NY/128), 128, SM_TOTAL>>>(
        yh, yl, Wkh, Wkl, bk, nullptr, nullptr, Kh, Kl, NY, HID, DIN, 1.0f);
    // V^T = Wv @ y^T + bv(row) -> bf16 hi/lo [1024,4096]
    gemm_bf16<<<dim3(NY/128, DOUT/128), 128, SM_TOTAL>>>(
        Wvh, Wvl, yh, yl, nullptr, bv, nullptr, VTh, VTl, DOUT, NY, DIN, 1.0f);
    // S = (Q @ K^T)/32      -> fp32         [4096,4096]
    gemm_bf16<<<dim3(NY/128, NX/128), 128, SM_TOTAL>>>(
        Qh, Ql, Kh, Kl, nullptr, nullptr, S, nullptr, nullptr, NX, NY, HID, inv_sqrt_h);
    // softmax rows -> attn hi/lo bf16
    softmax_rows_kernel<<<NX, 256>>>(S, Ph, Pl, NY);
    // out = attn @ V = P @ VT^T -> fp32     [4096,1024]
    gemm_bf16<<<dim3(DOUT/128, NX/128), 128, SM_TOTAL>>>(
        Ph, Pl, VTh, VTl, nullptr, nullptr, out, nullptr, nullptr, NX, DOUT, NY, 1.0f);
}

// round 16
// speedup vs baseline: 1.4246x; 1.3435x over previous
#include <cuda_runtime.h>
#include <cuda_fp16.h>
#include <math.h>
#include <stdint.h>

// Problem dims (fixed by the dataset)
#define NX   4096
#define NY   4096
#define DIN  1024
#define HID  1024
#define DOUT 1024

// ---------------------------------------------------------------------------
// Scratch: __device__ globals (allocation-free)
// A-side operands need hi only; B-side operands need hi+lo (22-bit).
// ---------------------------------------------------------------------------
__device__ half g_xh [(size_t)NX * DIN];
__device__ half g_yh [(size_t)NY * DIN],  g_yl [(size_t)NY * DIN];
__device__ half g_Wqh[(size_t)HID * DIN], g_Wql[(size_t)HID * DIN];
__device__ half g_Wkh[(size_t)HID * DIN], g_Wkl[(size_t)HID * DIN];
__device__ half g_Wvh[(size_t)DOUT * DIN];
__device__ half g_Qh [(size_t)NX * HID];
__device__ half g_Kh [(size_t)NY * HID],  g_Kl [(size_t)NY * HID];
__device__ half g_VTh[(size_t)DOUT * NY], g_VTl[(size_t)DOUT * NY];
__device__ half g_Ph [(size_t)NX * NY];
__device__ float g_S [(size_t)NX * NY];

// ---------------------------------------------------------------------------
// Helpers
// ---------------------------------------------------------------------------
__device__ __forceinline__ uint32_t smem_u32(const void* p) {
    uint32_t a;
    asm("{ .reg .u64 t; cvta.to.shared.u64 t, %1; cvt.u32.u64 %0, t; }" : "=r"(a) : "l"(p));
    return a;
}
__device__ __forceinline__ void ldm_x4(uint32_t* r, uint32_t addr) {
    asm volatile("ldmatrix.sync.aligned.m8n8.x4.shared.b16 {%0,%1,%2,%3}, [%4];"
                 : "=r"(r[0]), "=r"(r[1]), "=r"(r[2]), "=r"(r[3]) : "r"(addr));
}
__device__ __forceinline__ void mma_f16(float* c, const uint32_t* a,
                                        uint32_t b0, uint32_t b1) {
    asm volatile(
        "mma.sync.aligned.m16n8k16.row.col.f32.f16.f16.f32 "
        "{%0,%1,%2,%3}, {%4,%5,%6,%7}, {%8,%9}, {%0,%1,%2,%3};"
        : "+f"(c[0]), "+f"(c[1]), "+f"(c[2]), "+f"(c[3])
        : "r"(a[0]), "r"(a[1]), "r"(a[2]), "r"(a[3]), "r"(b0), "r"(b1));
}
// fp32 pair -> (hi f16x2, lo f16x2); x lands in the low 16 bits
__device__ __forceinline__ void cvt_split_f16(float x, float y, uint32_t& h, uint32_t& l) {
    asm("cvt.rn.f16x2.f32 %0, %1, %2;" : "=r"(h) : "f"(y), "f"(x));
    __half2 hh = *reinterpret_cast<__half2*>(&h);
    float hx = __low2float(hh);
    float hy = __high2float(hh);
    asm("cvt.rn.f16x2.f32 %0, %1, %2;" : "=r"(l) : "f"(y - hy), "f"(x - hx));
}
__device__ __forceinline__ void cpa16(uint32_t d, const void* s) {
    asm volatile("cp.async.cg.shared.global [%0], [%1], 16;" :: "r"(d), "l"(s) : "memory");
}
#define CP_COMMIT() asm volatile("cp.async.commit_group;" ::: "memory")
#define CP_WAIT0()  asm volatile("cp.async.wait_group 0;" ::: "memory")

// ---------------------------------------------------------------------------
// Fused elementwise fp32 -> (hi[, lo]) f16 split, up to 3 tensors per launch
// (lo pointer may be null -> hi-only split). Exactly TWO launches total so the
// ncu capture (-s 5 -c 1) lands on a GEMM.
// ---------------------------------------------------------------------------
__global__ __launch_bounds__(256)
void split3_kernel(const float* __restrict__ p0, half* __restrict__ h0, half* __restrict__ l0, int n0,
                   const float* __restrict__ p1, half* __restrict__ h1, half* __restrict__ l1, int n1,
                   const float* __restrict__ p2, half* __restrict__ h2, half* __restrict__ l2, int n2)
{
    int i = blockIdx.x * 256 + threadIdx.x;
    const float* in; half *hi, *lo;
    if (i < n0)                { in = p0; hi = h0; lo = l0; }
    else if (i < n0 + n1)      { i -= n0; in = p1; hi = h1; lo = l1; }
    else if (i < n0 + n1 + n2) { i -= n0 + n1; in = p2; hi = h2; lo = l2; }
    else return;
    float4 v = reinterpret_cast<const float4*>(in)[i];
    uint32_t a0, b0, a1, b1;
    cvt_split_f16(v.x, v.y, a0, b0);
    cvt_split_f16(v.z, v.w, a1, b1);
    reinterpret_cast<uint2*>(hi)[i] = make_uint2(a0, a1);
    if (lo) reinterpret_cast<uint2*>(lo)[i] = make_uint2(b0, b1);
}

// ---------------------------------------------------------------------------
// fp16 2-term split tensor-core GEMM:
//   acc = Ah @ (Bh + Bl)^T ; v = scale*acc + bias_col[N] + bias_row[M]
//   outputs: Cf (fp32) and/or Ch (f16 hi) [+ Cl (f16 lo) if needed as B later]
// CTA tile 128x128, BK=32, 128 threads (4 warps, 2x2), warp tile 64x64,
// 2 CTAs/SM. Per product: 2 MMAs (ah*bh + ah*bl) instead of 3 -> -33% MMA work.
// Flattened (kk,ng) steps with double-buffered B-frag prefetch (R15 structure).
// ---------------------------------------------------------------------------
#define PITCH 40                        // f16 elems per smem row (80 B)
#define T_AHI 0
#define T_BHI (128 * PITCH * 2)         // 10240
#define T_BLO (2 * 128 * PITCH * 2)     // 20480
#define STAGE_BYTES (3 * 128 * PITCH * 2)   // 30720
#define SM_TOTAL (2 * STAGE_BYTES)          // 61440

__global__ __launch_bounds__(128, 2)
void gemm_f16(const half* __restrict__ Ah,
              const half* __restrict__ Bh, const half* __restrict__ Bl,
              const float* __restrict__ bias_col, const float* __restrict__ bias_row,
              float* __restrict__ Cf, half* __restrict__ Ch, half* __restrict__ Cl,
              int M, int N, int K, float scale)
{
    extern __shared__ __align__(128) char smem[];
    const uint32_t sbase = smem_u32(smem);

    const int tid    = threadIdx.x;
    const int lane   = tid & 31;
    const int wid    = tid >> 5;        // 0..3
    const int warp_m = wid & 1;         // 2 slabs of 64 rows
    const int warp_n = wid >> 1;        // 2 slabs of 64 cols
    const int row0   = blockIdx.y * 128;
    const int col0   = blockIdx.x * 128;

    const half* pAh = Ah + (size_t)row0 * K;
    const half* pBh = Bh + (size_t)col0 * K;
    const half* pBl = Bl + (size_t)col0 * K;

    // loader geometry: base row = tid>>2 (0..31), 4 row-steps of 32; seg 16B
    const int l_r  = tid >> 2;
    const int l_sg = (tid & 3) * 8;

    float acc[4][8][4];
#pragma unroll
    for (int mf = 0; mf < 4; mf++)
#pragma unroll
        for (int nf = 0; nf < 8; nf++)
#pragma unroll
            for (int e = 0; e < 4; e++) acc[mf][nf][e] = 0.0f;

    // ldmatrix addressing (validated geometry)
    const int a_row  = lane & 15;
    const int a_kh   = (lane >> 4) << 3;
    const int bg     = lane >> 3;
    const int b_nrow = ((bg >> 1) << 3) + (lane & 7);
    const int b_kh   = (bg & 1) << 3;

    const int nch = K >> 5;

    auto issue = [&](int c) {
        const uint32_t st = sbase + (c & 1) * STAGE_BYTES;
        const int kofs = c * 32;
#pragma unroll
        for (int rt = 0; rt < 4; rt++) {
            const int r = l_r + rt * 32;
            const size_t go = (size_t)r * K + kofs + l_sg;
            const uint32_t so = (uint32_t)(r * PITCH + l_sg) * 2;
            cpa16(st + T_AHI + so, pAh + go);
            cpa16(st + T_BHI + so, pBh + go);
            cpa16(st + T_BLO + so, pBl + go);
        }
    };

    issue(0); CP_COMMIT();

    uint32_t ah[4][4];
    uint32_t bh[2][4], bl[2][4];

    for (int c = 0; c < nch; c++) {
        CP_WAIT0();                 // chunk c (sole pending group) has landed
        __syncthreads();            // chunk c visible; other stage reusable
        if (c + 1 < nch) { issue(c + 1); CP_COMMIT(); }   // other stage — safe

        const uint32_t st = sbase + (c & 1) * STAGE_BYTES;

        // head loads: A frags for kk=0, B frags for step 0
#pragma unroll
        for (int mf = 0; mf < 4; mf++) {
            uint32_t ra = st + ((warp_m * 64 + mf * 16 + a_row) * PITCH + a_kh) * 2;
            ldm_x4(ah[mf], ra + T_AHI);
        }
        {
            uint32_t rb = st + ((warp_n * 64 + b_nrow) * PITCH + b_kh) * 2;
            ldm_x4(bh[0], rb + T_BHI);
            ldm_x4(bl[0], rb + T_BLO);
        }

        // 8 flattened steps: t -> (kk = (t>>2)*16, ng = t&3)
#pragma unroll
        for (int t = 0; t < 8; t++) {
            const int cur = t & 1, nxt = cur ^ 1;
            const int ng  = t & 3;

            // prefetch B frags for step t+1 (lands under this step's MMAs)
            if (t < 7) {
                const int kkn = ((t + 1) >> 2) * 16;
                const int ngn = (t + 1) & 3;
                uint32_t rb = st + ((warp_n * 64 + ngn * 16 + b_nrow) * PITCH + kkn + b_kh) * 2;
                ldm_x4(bh[nxt], rb + T_BHI);
                ldm_x4(bl[nxt], rb + T_BLO);
            }
            // A frags for kk=16 at the kk boundary
            if (t == 4) {
#pragma unroll
                for (int mf = 0; mf < 4; mf++) {
                    uint32_t ra = st + ((warp_m * 64 + mf * 16 + a_row) * PITCH + 16 + a_kh) * 2;
                    ldm_x4(ah[mf], ra + T_AHI);
                }
            }

            // 16 MMAs: ah*bh then ah*bl (same-acc reuse distance 8)
#pragma unroll
            for (int s = 0; s < 2; s++)
#pragma unroll
                for (int mf = 0; mf < 4; mf++)
                    mma_f16(acc[mf][2 * ng + s], ah[mf], bh[cur][2 * s], bh[cur][2 * s + 1]);
#pragma unroll
            for (int s = 0; s < 2; s++)
#pragma unroll
                for (int mf = 0; mf < 4; mf++)
                    mma_f16(acc[mf][2 * ng + s], ah[mf], bl[cur][2 * s], bl[cur][2 * s + 1]);
        }
    }

    // ---- epilogue ----
    const int mrow = lane >> 2;
    const int ncol = (lane & 3) * 2;
#pragma unroll
    for (int mf = 0; mf < 4; mf++) {
        const int m0 = row0 + warp_m * 64 + mf * 16 + mrow;
        const float br0 = bias_row ? bias_row[m0]     : 0.0f;
        const float br8 = bias_row ? bias_row[m0 + 8] : 0.0f;
#pragma unroll
        for (int nf = 0; nf < 8; nf++) {
            const int n = col0 + warp_n * 64 + nf * 8 + ncol;
            float bc0 = 0.0f, bc1 = 0.0f;
            if (bias_col) { bc0 = bias_col[n]; bc1 = bias_col[n + 1]; }
            float* cc = acc[mf][nf];
            float v00 = cc[0] * scale + bc0 + br0;
            float v01 = cc[1] * scale + bc1 + br0;
            float v10 = cc[2] * scale + bc0 + br8;
            float v11 = cc[3] * scale + bc1 + br8;
            if (Cf) {
                *reinterpret_cast<float2*>(Cf + (size_t)m0 * N + n)       = make_float2(v00, v01);
                *reinterpret_cast<float2*>(Cf + (size_t)(m0 + 8) * N + n) = make_float2(v10, v11);
            }
            if (Ch) {
                uint32_t h, l;
                cvt_split_f16(v00, v01, h, l);
                *reinterpret_cast<uint32_t*>(Ch + (size_t)m0 * N + n) = h;
                if (Cl) *reinterpret_cast<uint32_t*>(Cl + (size_t)m0 * N + n) = l;
                cvt_split_f16(v10, v11, h, l);
                *reinterpret_cast<uint32_t*>(Ch + (size_t)(m0 + 8) * N + n) = h;
                if (Cl) *reinterpret_cast<uint32_t*>(Cl + (size_t)(m0 + 8) * N + n) = l;
            }
        }
    }
}

// ---------------------------------------------------------------------------
// Row softmax over N=4096 fp32 scores -> f16 probabilities (hi only; P is
// always an A-side operand)
// ---------------------------------------------------------------------------
__device__ __forceinline__ float warp_max(float v) {
#pragma unroll
    for (int o = 16; o > 0; o >>= 1) v = fmaxf(v, __shfl_xor_sync(0xffffffffu, v, o));
    return v;
}
__device__ __forceinline__ float warp_sum(float v) {
#pragma unroll
    for (int o = 16; o > 0; o >>= 1) v += __shfl_xor_sync(0xffffffffu, v, o);
    return v;
}

__global__ __launch_bounds__(256)
void softmax_rows_kernel(const float* __restrict__ S, half* __restrict__ Ph, int N)
{
    constexpr int T = 256;
    constexpr int PER = 4096 / T;
    const int row = blockIdx.x;
    const float* p = S + (size_t)row * N;
    half* ph = Ph + (size_t)row * N;
    const int tid = threadIdx.x;
    const int wid = tid >> 5, lid = tid & 31;
    __shared__ float red[8];

    float v[PER];
    float mx = -INFINITY;
#pragma unroll
    for (int i = 0; i < PER; i++) { v[i] = p[tid + i * T]; mx = fmaxf(mx, v[i]); }
    mx = warp_max(mx);
    if (lid == 0) red[wid] = mx;
    __syncthreads();
    { float m = (lid < 8) ? red[lid] : -INFINITY; m = warp_max(m); mx = __shfl_sync(0xffffffffu, m, 0); }

    float sum = 0.0f;
#pragma unroll
    for (int i = 0; i < PER; i++) { v[i] = __expf(v[i] - mx); sum += v[i]; }
    sum = warp_sum(sum);
    __syncthreads();
    if (lid == 0) red[wid] = sum;
    __syncthreads();
    { float s = (lid < 8) ? red[lid] : 0.0f; s = warp_sum(s); sum = __shfl_sync(0xffffffffu, s, 0); }

    const float inv = 1.0f / sum;
#pragma unroll
    for (int i = 0; i < PER; i++)
        ph[tid + i * T] = __float2half_rn(v[i] * inv);
}

// ---------------------------------------------------------------------------
// kernel_launch
// ---------------------------------------------------------------------------
extern "C" void kernel_launch(void* const* d_in, const int* in_sizes, int n_in,
                              void* d_out, int out_size)
{
    (void)in_sizes; (void)n_in; (void)out_size;
    const float* x  = (const float*)d_in[0];
    const float* y  = (const float*)d_in[1];
    const float* Wq = (const float*)d_in[2];
    const float* bq = (const float*)d_in[3];
    const float* Wk = (const float*)d_in[4];
    const float* bk = (const float*)d_in[5];
    const float* Wv = (const float*)d_in[6];
    const float* bv = (const float*)d_in[7];
    float* out = (float*)d_out;

    half *xh, *yh, *yl, *Wqh, *Wql, *Wkh, *Wkl, *Wvh;
    half *Qh, *Kh, *Kl, *VTh, *VTl, *Ph;
    float* S;
    cudaGetSymbolAddress((void**)&xh,  g_xh);
    cudaGetSymbolAddress((void**)&yh,  g_yh);  cudaGetSymbolAddress((void**)&yl,  g_yl);
    cudaGetSymbolAddress((void**)&Wqh, g_Wqh); cudaGetSymbolAddress((void**)&Wql, g_Wql);
    cudaGetSymbolAddress((void**)&Wkh, g_Wkh); cudaGetSymbolAddress((void**)&Wkl, g_Wkl);
    cudaGetSymbolAddress((void**)&Wvh, g_Wvh);
    cudaGetSymbolAddress((void**)&Qh,  g_Qh);
    cudaGetSymbolAddress((void**)&Kh,  g_Kh);  cudaGetSymbolAddress((void**)&Kl,  g_Kl);
    cudaGetSymbolAddress((void**)&VTh, g_VTh); cudaGetSymbolAddress((void**)&VTl, g_VTl);
    cudaGetSymbolAddress((void**)&Ph,  g_Ph);
    cudaGetSymbolAddress((void**)&S,   g_S);

    cudaFuncSetAttribute(gemm_f16, cudaFuncAttributeMaxDynamicSharedMemorySize, SM_TOTAL);

    const float inv_sqrt_h = 1.0f / 32.0f;

    // Pre-split inputs — exactly TWO launches.
    // A-side-only tensors (x, Wv) need hi only; B-side (Wq, Wk, y) need hi+lo.
    {
        const int nx4 = NX * DIN / 4, ny4 = NY * DIN / 4, nw4 = HID * DIN / 4;
        int totA = nx4 + nw4 + nw4;
        split3_kernel<<<(totA + 255) / 256, 256>>>(
            x, xh, nullptr, nx4, Wq, Wqh, Wql, nw4, Wk, Wkh, Wkl, nw4);
        int totB = ny4 + nw4;
        split3_kernel<<<(totB + 255) / 256, 256>>>(
            y, yh, yl, ny4, Wv, Wvh, nullptr, nw4, nullptr, nullptr, nullptr, 0);
    }

    // Q = x @ Wq^T + bq      -> f16 hi only  [4096,1024]  (A-side later)
    gemm_f16<<<dim3(HID/128, NX/128), 128, SM_TOTAL>>>(
        xh, Wqh, Wql, bq, nullptr, nullptr, Qh, nullptr, NX, HID, DIN, 1.0f);
    // K = y @ Wk^T + bk      -> f16 hi+lo    [4096,1024]  (B-side later)
    gemm_f16<<<dim3(HID/128, NY/128), 128, SM_TOTAL>>>(
        yh, Wkh, Wkl, bk, nullptr, nullptr, Kh, Kl, NY, HID, DIN, 1.0f);
    // V^T = Wv @ y^T + bv(row) -> f16 hi+lo  [1024,4096]  (B-side later)
    gemm_f16<<<dim3(NY/128, DOUT/128), 128, SM_TOTAL>>>(
        Wvh, yh, yl, nullptr, bv, nullptr, VTh, VTl, DOUT, NY, DIN, 1.0f);
    // S = (Q @ K^T)/32       -> fp32         [4096,4096]
    gemm_f16<<<dim3(NY/128, NX/128), 128, SM_TOTAL>>>(
        Qh, Kh, Kl, nullptr, nullptr, S, nullptr, nullptr, NX, NY, HID, inv_sqrt_h);
    // softmax rows -> attn f16 (hi only)
    softmax_rows_kernel<<<NX, 256>>>(S, Ph, NY);
    // out = attn @ V = P @ VT^T -> fp32      [4096,1024]
    gemm_f16<<<dim3(DOUT/128, NX/128), 128, SM_TOTAL>>>(
        Ph, VTh, VTl, nullptr, nullptr, out, nullptr, nullptr, NX, DOUT, NY, 1.0f);
}

// round 17
// speedup vs baseline: 1.4398x; 1.0106x over previous
#include <cuda_runtime.h>
#include <cuda_fp16.h>
#include <math.h>
#include <stdint.h>

// Problem dims (fixed by the dataset)
#define NX   4096
#define NY   4096
#define DIN  1024
#define HID  1024
#define DOUT 1024

// ---------------------------------------------------------------------------
// Scratch: __device__ globals (allocation-free)
// A-side operands need hi only; B-side operands need hi+lo (22-bit).
// ---------------------------------------------------------------------------
__device__ half g_xh [(size_t)NX * DIN];
__device__ half g_yh [(size_t)NY * DIN],  g_yl [(size_t)NY * DIN];
__device__ half g_Wqh[(size_t)HID * DIN], g_Wql[(size_t)HID * DIN];
__device__ half g_Wkh[(size_t)HID * DIN], g_Wkl[(size_t)HID * DIN];
__device__ half g_Wvh[(size_t)DOUT * DIN];
__device__ half g_Qh [(size_t)NX * HID];
__device__ half g_Kh [(size_t)NY * HID],  g_Kl [(size_t)NY * HID];
__device__ half g_VTh[(size_t)DOUT * NY], g_VTl[(size_t)DOUT * NY];
__device__ half g_Ph [(size_t)NX * NY];
__device__ float g_S [(size_t)NX * NY];

// ---------------------------------------------------------------------------
// Helpers
// ---------------------------------------------------------------------------
__device__ __forceinline__ uint32_t smem_u32(const void* p) {
    uint32_t a;
    asm("{ .reg .u64 t; cvta.to.shared.u64 t, %1; cvt.u32.u64 %0, t; }" : "=r"(a) : "l"(p));
    return a;
}
__device__ __forceinline__ void ldm_x4(uint32_t* r, uint32_t addr) {
    asm volatile("ldmatrix.sync.aligned.m8n8.x4.shared.b16 {%0,%1,%2,%3}, [%4];"
                 : "=r"(r[0]), "=r"(r[1]), "=r"(r[2]), "=r"(r[3]) : "r"(addr));
}
__device__ __forceinline__ void mma_f16(float* c, const uint32_t* a,
                                        uint32_t b0, uint32_t b1) {
    asm volatile(
        "mma.sync.aligned.m16n8k16.row.col.f32.f16.f16.f32 "
        "{%0,%1,%2,%3}, {%4,%5,%6,%7}, {%8,%9}, {%0,%1,%2,%3};"
        : "+f"(c[0]), "+f"(c[1]), "+f"(c[2]), "+f"(c[3])
        : "r"(a[0]), "r"(a[1]), "r"(a[2]), "r"(a[3]), "r"(b0), "r"(b1));
}
// fp32 pair -> (hi f16x2, lo f16x2); x lands in the low 16 bits
__device__ __forceinline__ void cvt_split_f16(float x, float y, uint32_t& h, uint32_t& l) {
    asm("cvt.rn.f16x2.f32 %0, %1, %2;" : "=r"(h) : "f"(y), "f"(x));
    __half2 hh = *reinterpret_cast<__half2*>(&h);
    float hx = __low2float(hh);
    float hy = __high2float(hh);
    asm("cvt.rn.f16x2.f32 %0, %1, %2;" : "=r"(l) : "f"(y - hy), "f"(x - hx));
}
__device__ __forceinline__ void cpa16(uint32_t d, const void* s) {
    asm volatile("cp.async.cg.shared.global [%0], [%1], 16;" :: "r"(d), "l"(s) : "memory");
}
#define CP_COMMIT() asm volatile("cp.async.commit_group;" ::: "memory")
#define CP_WAIT0()  asm volatile("cp.async.wait_group 0;" ::: "memory")

// ---------------------------------------------------------------------------
// Fused elementwise fp32 -> (hi[, lo]) f16 split, up to 3 tensors per launch
// (lo pointer may be null -> hi-only). Exactly TWO launches total.
// ---------------------------------------------------------------------------
__global__ __launch_bounds__(256)
void split3_kernel(const float* __restrict__ p0, half* __restrict__ h0, half* __restrict__ l0, int n0,
                   const float* __restrict__ p1, half* __restrict__ h1, half* __restrict__ l1, int n1,
                   const float* __restrict__ p2, half* __restrict__ h2, half* __restrict__ l2, int n2)
{
    int i = blockIdx.x * 256 + threadIdx.x;
    const float* in; half *hi, *lo;
    if (i < n0)                { in = p0; hi = h0; lo = l0; }
    else if (i < n0 + n1)      { i -= n0; in = p1; hi = h1; lo = l1; }
    else if (i < n0 + n1 + n2) { i -= n0 + n1; in = p2; hi = h2; lo = l2; }
    else return;
    float4 v = reinterpret_cast<const float4*>(in)[i];
    uint32_t a0, b0, a1, b1;
    cvt_split_f16(v.x, v.y, a0, b0);
    cvt_split_f16(v.z, v.w, a1, b1);
    reinterpret_cast<uint2*>(hi)[i] = make_uint2(a0, a1);
    if (lo) reinterpret_cast<uint2*>(lo)[i] = make_uint2(b0, b1);
}

// ---------------------------------------------------------------------------
// fp16 2-term split tensor-core GEMM:
//   acc = Ah @ (Bh + Bl)^T ; v = scale*acc + bias_col[N] + bias_row[M]
// CTA tile 128x128, BK=64 (chunks halved -> per-chunk overhead amortized),
// 128 threads (4 warps, 2x2), warp tile 64x64, 2 CTAs/SM.
// 2-stage cp.async pipeline, lookahead 1, one barrier per chunk.
// In-chunk: 16 flattened steps with double-buffered B-frag prefetch.
// ---------------------------------------------------------------------------
#define PITCH 72                        // f16 elems per smem row (144 B)
#define T_AHI 0
#define T_BHI (128 * PITCH * 2)         // 18432
#define T_BLO (2 * 128 * PITCH * 2)     // 36864
#define STAGE_BYTES (3 * 128 * PITCH * 2)   // 55296
#define SM_TOTAL (2 * STAGE_BYTES)          // 110592

__global__ __launch_bounds__(128, 2)
void gemm_f16(const half* __restrict__ Ah,
              const half* __restrict__ Bh, const half* __restrict__ Bl,
              const float* __restrict__ bias_col, const float* __restrict__ bias_row,
              float* __restrict__ Cf, half* __restrict__ Ch, half* __restrict__ Cl,
              int M, int N, int K, float scale)
{
    extern __shared__ __align__(128) char smem[];
    const uint32_t sbase = smem_u32(smem);

    const int tid    = threadIdx.x;
    const int lane   = tid & 31;
    const int wid    = tid >> 5;        // 0..3
    const int warp_m = wid & 1;         // 2 slabs of 64 rows
    const int warp_n = wid >> 1;        // 2 slabs of 64 cols
    const int row0   = blockIdx.y * 128;
    const int col0   = blockIdx.x * 128;

    const half* pAh = Ah + (size_t)row0 * K;
    const half* pBh = Bh + (size_t)col0 * K;
    const half* pBl = Bl + (size_t)col0 * K;

    // loader geometry (BK=64): row = tid>>3 (0..15), 8 row-steps of 16;
    // seg = (tid&7)*8 f16 (16B); 8 segs cover the 128-B row.
    const int l_r  = tid >> 3;
    const int l_sg = (tid & 7) * 8;

    float acc[4][8][4];
#pragma unroll
    for (int mf = 0; mf < 4; mf++)
#pragma unroll
        for (int nf = 0; nf < 8; nf++)
#pragma unroll
            for (int e = 0; e < 4; e++) acc[mf][nf][e] = 0.0f;

    // ldmatrix addressing (validated geometry)
    const int a_row  = lane & 15;
    const int a_kh   = (lane >> 4) << 3;
    const int bg     = lane >> 3;
    const int b_nrow = ((bg >> 1) << 3) + (lane & 7);
    const int b_kh   = (bg & 1) << 3;

    const int nch = K >> 6;             // BK = 64

    auto issue = [&](int c) {
        const uint32_t st = sbase + (c & 1) * STAGE_BYTES;
        const int kofs = c * 64;
#pragma unroll
        for (int rt = 0; rt < 8; rt++) {
            const int r = l_r + rt * 16;
            const size_t go = (size_t)r * K + kofs + l_sg;
            const uint32_t so = (uint32_t)(r * PITCH + l_sg) * 2;
            cpa16(st + T_AHI + so, pAh + go);
            cpa16(st + T_BHI + so, pBh + go);
            cpa16(st + T_BLO + so, pBl + go);
        }
    };

    issue(0); CP_COMMIT();

    uint32_t ah[4][4];
    uint32_t bh[2][4], bl[2][4];

    for (int c = 0; c < nch; c++) {
        CP_WAIT0();                 // chunk c (sole pending group) has landed
        __syncthreads();            // chunk c visible; other stage reusable
        if (c + 1 < nch) { issue(c + 1); CP_COMMIT(); }   // other stage — safe

        const uint32_t st = sbase + (c & 1) * STAGE_BYTES;

        // head loads: A frags for kk=0, B frags for step 0
#pragma unroll
        for (int mf = 0; mf < 4; mf++) {
            uint32_t ra = st + ((warp_m * 64 + mf * 16 + a_row) * PITCH + a_kh) * 2;
            ldm_x4(ah[mf], ra + T_AHI);
        }
        {
            uint32_t rb = st + ((warp_n * 64 + b_nrow) * PITCH + b_kh) * 2;
            ldm_x4(bh[0], rb + T_BHI);
            ldm_x4(bl[0], rb + T_BLO);
        }

        // 16 flattened steps: t -> (kk = (t>>2)*16, ng = t&3)
#pragma unroll
        for (int t = 0; t < 16; t++) {
            const int cur = t & 1, nxt = cur ^ 1;
            const int ng  = t & 3;
            const int kk  = (t >> 2) * 16;

            // prefetch B frags for step t+1 (lands under this step's MMAs)
            if (t < 15) {
                const int kkn = ((t + 1) >> 2) * 16;
                const int ngn = (t + 1) & 3;
                uint32_t rb = st + ((warp_n * 64 + ngn * 16 + b_nrow) * PITCH + kkn + b_kh) * 2;
                ldm_x4(bh[nxt], rb + T_BHI);
                ldm_x4(bl[nxt], rb + T_BLO);
            }
            // A frags at each kk boundary (t = 4, 8, 12)
            if (t > 0 && (t & 3) == 0) {
#pragma unroll
                for (int mf = 0; mf < 4; mf++) {
                    uint32_t ra = st + ((warp_m * 64 + mf * 16 + a_row) * PITCH + kk + a_kh) * 2;
                    ldm_x4(ah[mf], ra + T_AHI);
                }
            }

            // 16 MMAs: ah*bh then ah*bl (same-acc reuse distance 8)
#pragma unroll
            for (int s = 0; s < 2; s++)
#pragma unroll
                for (int mf = 0; mf < 4; mf++)
                    mma_f16(acc[mf][2 * ng + s], ah[mf], bh[cur][2 * s], bh[cur][2 * s + 1]);
#pragma unroll
            for (int s = 0; s < 2; s++)
#pragma unroll
                for (int mf = 0; mf < 4; mf++)
                    mma_f16(acc[mf][2 * ng + s], ah[mf], bl[cur][2 * s], bl[cur][2 * s + 1]);
        }
    }

    // ---- epilogue ----
    const int mrow = lane >> 2;
    const int ncol = (lane & 3) * 2;
#pragma unroll
    for (int mf = 0; mf < 4; mf++) {
        const int m0 = row0 + warp_m * 64 + mf * 16 + mrow;
        const float br0 = bias_row ? bias_row[m0]     : 0.0f;
        const float br8 = bias_row ? bias_row[m0 + 8] : 0.0f;
#pragma unroll
        for (int nf = 0; nf < 8; nf++) {
            const int n = col0 + warp_n * 64 + nf * 8 + ncol;
            float bc0 = 0.0f, bc1 = 0.0f;
            if (bias_col) { bc0 = bias_col[n]; bc1 = bias_col[n + 1]; }
            float* cc = acc[mf][nf];
            float v00 = cc[0] * scale + bc0 + br0;
            float v01 = cc[1] * scale + bc1 + br0;
            float v10 = cc[2] * scale + bc0 + br8;
            float v11 = cc[3] * scale + bc1 + br8;
            if (Cf) {
                *reinterpret_cast<float2*>(Cf + (size_t)m0 * N + n)       = make_float2(v00, v01);
                *reinterpret_cast<float2*>(Cf + (size_t)(m0 + 8) * N + n) = make_float2(v10, v11);
            }
            if (Ch) {
                uint32_t h, l;
                cvt_split_f16(v00, v01, h, l);
                *reinterpret_cast<uint32_t*>(Ch + (size_t)m0 * N + n) = h;
                if (Cl) *reinterpret_cast<uint32_t*>(Cl + (size_t)m0 * N + n) = l;
                cvt_split_f16(v10, v11, h, l);
                *reinterpret_cast<uint32_t*>(Ch + (size_t)(m0 + 8) * N + n) = h;
                if (Cl) *reinterpret_cast<uint32_t*>(Cl + (size_t)(m0 + 8) * N + n) = l;
            }
        }
    }
}

// ---------------------------------------------------------------------------
// Row softmax over N=4096 fp32 scores -> f16 probabilities (hi only)
// ---------------------------------------------------------------------------
__device__ __forceinline__ float warp_max(float v) {
#pragma unroll
    for (int o = 16; o > 0; o >>= 1) v = fmaxf(v, __shfl_xor_sync(0xffffffffu, v, o));
    return v;
}
__device__ __forceinline__ float warp_sum(float v) {
#pragma unroll
    for (int o = 16; o > 0; o >>= 1) v += __shfl_xor_sync(0xffffffffu, v, o);
    return v;
}

__global__ __launch_bounds__(256)
void softmax_rows_kernel(const float* __restrict__ S, half* __restrict__ Ph, int N)
{
    constexpr int T = 256;
    constexpr int PER = 4096 / T;
    const int row = blockIdx.x;
    const float* p = S + (size_t)row * N;
    half* ph = Ph + (size_t)row * N;
    const int tid = threadIdx.x;
    const int wid = tid >> 5, lid = tid & 31;
    __shared__ float red[8];

    float v[PER];
    float mx = -INFINITY;
#pragma unroll
    for (int i = 0; i < PER; i++) { v[i] = p[tid + i * T]; mx = fmaxf(mx, v[i]); }
    mx = warp_max(mx);
    if (lid == 0) red[wid] = mx;
    __syncthreads();
    { float m = (lid < 8) ? red[lid] : -INFINITY; m = warp_max(m); mx = __shfl_sync(0xffffffffu, m, 0); }

    float sum = 0.0f;
#pragma unroll
    for (int i = 0; i < PER; i++) { v[i] = __expf(v[i] - mx); sum += v[i]; }
    sum = warp_sum(sum);
    __syncthreads();
    if (lid == 0) red[wid] = sum;
    __syncthreads();
    { float s = (lid < 8) ? red[lid] : 0.0f; s = warp_sum(s); sum = __shfl_sync(0xffffffffu, s, 0); }

    const float inv = 1.0f / sum;
#pragma unroll
    for (int i = 0; i < PER; i++)
        ph[tid + i * T] = __float2half_rn(v[i] * inv);
}

// ---------------------------------------------------------------------------
// kernel_launch
// ---------------------------------------------------------------------------
extern "C" void kernel_launch(void* const* d_in, const int* in_sizes, int n_in,
                              void* d_out, int out_size)
{
    (void)in_sizes; (void)n_in; (void)out_size;
    const float* x  = (const float*)d_in[0];
    const float* y  = (const float*)d_in[1];
    const float* Wq = (const float*)d_in[2];
    const float* bq = (const float*)d_in[3];
    const float* Wk = (const float*)d_in[4];
    const float* bk = (const float*)d_in[5];
    const float* Wv = (const float*)d_in[6];
    const float* bv = (const float*)d_in[7];
    float* out = (float*)d_out;

    half *xh, *yh, *yl, *Wqh, *Wql, *Wkh, *Wkl, *Wvh;
    half *Qh, *Kh, *Kl, *VTh, *VTl, *Ph;
    float* S;
    cudaGetSymbolAddress((void**)&xh,  g_xh);
    cudaGetSymbolAddress((void**)&yh,  g_yh);  cudaGetSymbolAddress((void**)&yl,  g_yl);
    cudaGetSymbolAddress((void**)&Wqh, g_Wqh); cudaGetSymbolAddress((void**)&Wql, g_Wql);
    cudaGetSymbolAddress((void**)&Wkh, g_Wkh); cudaGetSymbolAddress((void**)&Wkl, g_Wkl);
    cudaGetSymbolAddress((void**)&Wvh, g_Wvh);
    cudaGetSymbolAddress((void**)&Qh,  g_Qh);
    cudaGetSymbolAddress((void**)&Kh,  g_Kh);  cudaGetSymbolAddress((void**)&Kl,  g_Kl);
    cudaGetSymbolAddress((void**)&VTh, g_VTh); cudaGetSymbolAddress((void**)&VTl, g_VTl);
    cudaGetSymbolAddress((void**)&Ph,  g_Ph);
    cudaGetSymbolAddress((void**)&S,   g_S);

    cudaFuncSetAttribute(gemm_f16, cudaFuncAttributeMaxDynamicSharedMemorySize, SM_TOTAL);

    const float inv_sqrt_h = 1.0f / 32.0f;

    // Pre-split inputs — exactly TWO launches.
    // A-side-only tensors (x, Wv) need hi only; B-side (Wq, Wk, y) need hi+lo.
    {
        const int nx4 = NX * DIN / 4, ny4 = NY * DIN / 4, nw4 = HID * DIN / 4;
        int totA = nx4 + nw4 + nw4;
        split3_kernel<<<(totA + 255) / 256, 256>>>(
            x, xh, nullptr, nx4, Wq, Wqh, Wql, nw4, Wk, Wkh, Wkl, nw4);
        int totB = ny4 + nw4;
        split3_kernel<<<(totB + 255) / 256, 256>>>(
            y, yh, yl, ny4, Wv, Wvh, nullptr, nw4, nullptr, nullptr, nullptr, 0);
    }

    // Q = x @ Wq^T + bq      -> f16 hi only  [4096,1024]  (A-side later)
    gemm_f16<<<dim3(HID/128, NX/128), 128, SM_TOTAL>>>(
        xh, Wqh, Wql, bq, nullptr, nullptr, Qh, nullptr, NX, HID, DIN, 1.0f);
    // K = y @ Wk^T + bk      -> f16 hi+lo    [4096,1024]  (B-side later)
    gemm_f16<<<dim3(HID/128, NY/128), 128, SM_TOTAL>>>(
        yh, Wkh, Wkl, bk, nullptr, nullptr, Kh, Kl, NY, HID, DIN, 1.0f);
    // V^T = Wv @ y^T + bv(row) -> f16 hi+lo  [1024,4096]  (B-side later)
    gemm_f16<<<dim3(NY/128, DOUT/128), 128, SM_TOTAL>>>(
        Wvh, yh, yl, nullptr, bv, nullptr, VTh, VTl, DOUT, NY, DIN, 1.0f);
    // S = (Q @ K^T)/32       -> fp32         [4096,4096]
    gemm_f16<<<dim3(NY/128, NX/128), 128, SM_TOTAL>>>(
        Qh, Kh, Kl, nullptr, nullptr, S, nullptr, nullptr, NX, NY, HID, inv_sqrt_h);
    // softmax rows -> attn f16 (hi only)
    softmax_rows_kernel<<<NX, 256>>>(S, Ph, NY);
    // out = attn @ V = P @ VT^T -> fp32      [4096,1024]
    gemm_f16<<<dim3(DOUT/128, NX/128), 128, SM_TOTAL>>>(
        Ph, VTh, VTl, nullptr, nullptr, out, nullptr, nullptr, NX, DOUT, NY, 1.0f);
}